// round 8
// baseline (speedup 1.0000x reference)
#include <cuda_runtime.h>
#include <cstdint>

// FOFE encoding:
//   out[b,s,v] = sum_k alpha^(W-1-k) * [sents[b,s,k] == v],  V=512, W=20
// TMA-output pipeline: per-warp double-buffered 2KB smem rows.
//   - atomicAdd scatter into buf b while cp.async.bulk drains buf b^1 to GMEM
//   - dirty-slot clearing: only the <=20 slots touched 2 rows ago are re-zeroed
//   - weights hoisted per warp, chars prefetched one row ahead
// Store path bypasses LSU entirely (no LDS readback, no STG).

#define FOFE_V 512
#define FOFE_W 20
#define WARPS_PER_BLOCK 8
#define NUM_BLOCKS 1024     // 8192 warps; 65536 rows -> 8 rows/warp, 7 blocks/SM

__device__ __forceinline__ uint32_t smem_u32(const void* p) {
    return (uint32_t)__cvta_generic_to_shared(p);
}

__global__ void __launch_bounds__(WARPS_PER_BLOCK * 32)
fofe_kernel(const int* __restrict__ sents,
            const int* __restrict__ lengths,
            const float* __restrict__ forgetting,
            float* __restrict__ out,
            int n_rows, int tail_n) {
    __shared__ __align__(16) float sh[WARPS_PER_BLOCK][2][FOFE_V];

    const int warp = threadIdx.x >> 5;
    const int lane = threadIdx.x & 31;

    // fused lengths tail (block 0, <=256 values)
    if (blockIdx.x == 0 && (int)threadIdx.x < tail_n) {
        out[(size_t)n_rows * FOFE_V + threadIdx.x] = (float)lengths[threadIdx.x];
    }

    // hoisted per-warp decay weight: w = alpha^(W-1-lane) for lanes 0..19
    const float alpha = __ldg(forgetting);
    float w = 0.0f;
    if (lane < FOFE_W) {
        w = 1.0f;
        const int e = FOFE_W - 1 - lane;
        #pragma unroll
        for (int j = 0; j < FOFE_W - 1; j++) {
            if (j < e) w *= alpha;
        }
    }

    // zero both buffers once (8 x STS.128 per lane)
    float4* b4 = reinterpret_cast<float4*>(&sh[warp][0][0]);
    const float4 z4 = make_float4(0.f, 0.f, 0.f, 0.f);
    #pragma unroll
    for (int i = 0; i < 8; i++) b4[lane + i * 32] = z4;
    __syncwarp();

    const int gwarp  = blockIdx.x * WARPS_PER_BLOCK + warp;
    const int stride = gridDim.x * WARPS_PER_BLOCK;

    // prefetch chars for first row
    int c_cur = 0;
    if (gwarp < n_rows && lane < FOFE_W) {
        c_cur = __ldg(sents + (size_t)gwarp * FOFE_W + lane);
    }

    int c_last[2] = {-1, -1};   // char this lane wrote into buf b, 2 rows ago
    int it = 0;

    for (int row = gwarp; row < n_rows; row += stride, it++) {
        const int b = it & 1;
        float* buf = &sh[warp][b][0];

        // wait until TMA finished READING this buffer (allow 1 newer pending)
        if (lane == 0) {
            asm volatile("cp.async.bulk.wait_group.read 1;" ::: "memory");
        }
        __syncwarp();

        // clear only the slots dirtied 2 rows ago
        if (lane < FOFE_W && c_last[b] >= 0) buf[c_last[b]] = 0.0f;
        __syncwarp();

        // scatter-add this row
        if (lane < FOFE_W) atomicAdd(&buf[c_cur], w);
        c_last[b] = (lane < FOFE_W) ? c_cur : -1;

        // prefetch next row's chars (overlaps with fence/store)
        const int nrow = row + stride;
        if (nrow < n_rows && lane < FOFE_W) {
            c_cur = __ldg(sents + (size_t)nrow * FOFE_W + lane);
        }
        __syncwarp();

        // async bulk store: smem row -> gmem row (2KB), no LSU involvement
        if (lane == 0) {
            float* dst = out + (size_t)row * FOFE_V;
            asm volatile("fence.proxy.async.shared::cta;" ::: "memory");
            asm volatile(
                "cp.async.bulk.global.shared::cta.bulk_group [%0], [%1], %2;"
                :: "l"(dst), "r"(smem_u32(buf)), "n"(FOFE_V * 4) : "memory");
            asm volatile("cp.async.bulk.commit_group;" ::: "memory");
        }
    }

    // drain all outstanding bulk stores before exit (smem lifetime)
    if (lane == 0) {
        asm volatile("cp.async.bulk.wait_group 0;" ::: "memory");
    }
    __syncwarp();
}

extern "C" void kernel_launch(void* const* d_in, const int* in_sizes, int n_in,
                              void* d_out, int out_size) {
    const int*   sents      = (const int*)d_in[0];
    const int*   lengths    = (const int*)d_in[1];
    const float* forgetting = (const float*)d_in[2];
    float*       out        = (float*)d_out;

    const int n_rows = in_sizes[0] / FOFE_W;      // B*S
    const int B      = in_sizes[1];

    const long long main_elems = (long long)n_rows * FOFE_V;
    int tail_n = 0;
    if ((long long)out_size > main_elems) {
        long long t = (long long)out_size - main_elems;
        tail_n = (int)(t < B ? t : B);
        if (tail_n > 256) tail_n = 256;
    }

    const int threads = WARPS_PER_BLOCK * 32;
    fofe_kernel<<<NUM_BLOCKS, threads>>>(sents, lengths, forgetting, out,
                                         n_rows, tail_n);
}

// round 9
// speedup vs baseline: 1.2526x; 1.2526x over previous
#include <cuda_runtime.h>
#include <cstdint>

// FOFE encoding:
//   out[b,s,v] = sum_k alpha^(W-1-k) * [sents[b,s,k] == v],  V=512, W=20
// R2 body (warp-owns-row, smem accumulate, float4 stcs) but each warp
// processes 4 CONSECUTIVE rows: grid drops 8192 -> 2048 (13.8 -> 3.5 CTA
// waves), chars for all 4 rows loaded up-front (MLP=4), decay weights
// hoisted once per warp. Occupancy identical to R2 (8 warps/CTA, 16KB smem).

#define FOFE_V 512
#define FOFE_W 20
#define WARPS_PER_BLOCK 8
#define ROWS_PER_WARP 4

__global__ void __launch_bounds__(WARPS_PER_BLOCK * 32)
fofe_kernel(const int* __restrict__ sents,
            const int* __restrict__ lengths,
            const float* __restrict__ forgetting,
            float* __restrict__ out,
            int n_rows, int tail_n) {
    __shared__ float sh[WARPS_PER_BLOCK][FOFE_V];

    const int warp = threadIdx.x >> 5;
    const int lane = threadIdx.x & 31;
    const int wbase = (blockIdx.x * WARPS_PER_BLOCK + warp) * ROWS_PER_WARP;

    // fused lengths tail (block 0, <=256 values)
    if (blockIdx.x == 0 && (int)threadIdx.x < tail_n) {
        out[(size_t)n_rows * FOFE_V + threadIdx.x] = (float)lengths[threadIdx.x];
    }
    if (wbase >= n_rows) return;

    // hoisted per-warp decay weight: w = alpha^(W-1-lane) for lanes 0..19
    const float alpha = __ldg(forgetting);
    float w = 0.0f;
    if (lane < FOFE_W) {
        w = 1.0f;
        const int e = FOFE_W - 1 - lane;
        #pragma unroll
        for (int j = 0; j < FOFE_W - 1; j++) {
            if (j < e) w *= alpha;
        }
    }

    // front-batched char loads for all 4 rows (MLP=4)
    int c[ROWS_PER_WARP];
    if (lane < FOFE_W) {
        #pragma unroll
        for (int j = 0; j < ROWS_PER_WARP; j++) {
            const int r = wbase + j;
            if (r < n_rows) c[j] = __ldg(sents + (size_t)r * FOFE_W + lane);
        }
    }

    float* s = sh[warp];
    float4* s4 = reinterpret_cast<float4*>(s);
    const float4 z4 = make_float4(0.f, 0.f, 0.f, 0.f);

    #pragma unroll
    for (int j = 0; j < ROWS_PER_WARP; j++) {
        const int row = wbase + j;
        if (row >= n_rows) break;

        // zero 512 floats (4 x STS.128 per lane)
        #pragma unroll
        for (int i = 0; i < 4; i++) s4[lane + i * 32] = z4;
        __syncwarp();

        // scatter-add decay weights
        if (lane < FOFE_W) atomicAdd(&s[c[j]], w);
        __syncwarp();

        // stream out (4 x STG.128 per lane, evict-first)
        float4* orow = reinterpret_cast<float4*>(out + (size_t)row * FOFE_V);
        #pragma unroll
        for (int i = 0; i < 4; i++) {
            const int idx = lane + i * 32;
            __stcs(orow + idx, s4[idx]);
        }
        // no trailing sync needed: each lane re-zeroes only its own slots
        // (same-thread LDS->STS ordering), cross-lane visibility handled by
        // the two syncwarps above in the next iteration.
    }
}

extern "C" void kernel_launch(void* const* d_in, const int* in_sizes, int n_in,
                              void* d_out, int out_size) {
    const int*   sents      = (const int*)d_in[0];
    const int*   lengths    = (const int*)d_in[1];
    const float* forgetting = (const float*)d_in[2];
    float*       out        = (float*)d_out;

    const int n_rows = in_sizes[0] / FOFE_W;      // B*S
    const int B      = in_sizes[1];

    const long long main_elems = (long long)n_rows * FOFE_V;
    int tail_n = 0;
    if ((long long)out_size > main_elems) {
        long long t = (long long)out_size - main_elems;
        tail_n = (int)(t < B ? t : B);
        if (tail_n > 256) tail_n = 256;
    }

    const int threads = WARPS_PER_BLOCK * 32;
    const int rows_per_block = WARPS_PER_BLOCK * ROWS_PER_WARP;
    const int blocks = (n_rows + rows_per_block - 1) / rows_per_block;
    fofe_kernel<<<blocks, threads>>>(sents, lengths, forgetting, out,
                                     n_rows, tail_n);
}